// round 1
// baseline (speedup 1.0000x reference)
#include <cuda_runtime.h>

// Problem geometry: y_true / y_pred are [B=2, C=1, D=160, H=192, W=160] fp32.
#define Bsz 2
#define Dd  160
#define Hh  192
#define Ww  160
#define HW  (Hh * Ww)          // 30720
#define DHW (Dd * HW)          // 4915200
#define NTOT (Bsz * DHW)       // 9830400
#define RADI 4
#define INV_V (1.0f / 729.0f)
#define EPSL 1e-6f

#define CH 48   // H-chunk per block (192/48 = 4 chunks)
#define CD 40   // D-chunk per block (160/40 = 4 chunks)

// Scratch: 6 fields of N floats = 236 MB, as __device__ globals (no allocs).
__device__ float g_scratch[6][NTOT];

// ---------------------------------------------------------------------------
// Pass 1a: W-axis 9-wide box sum of t and p (replicate clamp), smem line tiles.
// blockDim = (160, 2): 2 lines per block. grid = B*D*H/2 = 30720.
// ---------------------------------------------------------------------------
template<int DST0, int DST1>
__global__ void box_w2(const float* __restrict__ a, const float* __restrict__ b) {
    __shared__ float sa[2][Ww], sb[2][Ww];
    const int ly = threadIdx.y;
    const int w  = threadIdx.x;
    const long base = (long)(blockIdx.x * 2 + ly) * Ww;
    sa[ly][w] = a[base + w];
    sb[ly][w] = b[base + w];
    __syncthreads();
    float s0 = 0.f, s1 = 0.f;
#pragma unroll
    for (int d = -RADI; d <= RADI; ++d) {
        int i = min(max(w + d, 0), Ww - 1);
        s0 += sa[ly][i];
        s1 += sb[ly][i];
    }
    g_scratch[DST0][base + w] = s0;
    g_scratch[DST1][base + w] = s1;
}

// ---------------------------------------------------------------------------
// Pass 1b: H-axis running box sum, 2 fields.
// blockDim = (160, 2): thread = one w-column of one (b,d) plane.
// grid = (B*D/2, H/CH).
// ---------------------------------------------------------------------------
template<int S0, int S1, int D0, int D1>
__global__ void box_h2() {
    const int w     = threadIdx.x;
    const int plane = blockIdx.x * 2 + threadIdx.y;  // [0, B*D)
    const int h0    = blockIdx.y * CH;
    const float* __restrict__ a = g_scratch[S0];
    const float* __restrict__ b = g_scratch[S1];
    float* __restrict__ oa = g_scratch[D0];
    float* __restrict__ ob = g_scratch[D1];
    const long pb = (long)plane * HW + w;

    float s0 = 0.f, s1 = 0.f;
#pragma unroll
    for (int d = -RADI; d <= RADI; ++d) {
        int hh = min(max(h0 + d, 0), Hh - 1);
        s0 += a[pb + (long)hh * Ww];
        s1 += b[pb + (long)hh * Ww];
    }
    oa[pb + (long)h0 * Ww] = s0;
    ob[pb + (long)h0 * Ww] = s1;
    for (int h = h0 + 1; h < h0 + CH; ++h) {
        int hp = min(h + RADI, Hh - 1);
        int hm = max(h - RADI - 1, 0);
        s0 += a[pb + (long)hp * Ww] - a[pb + (long)hm * Ww];
        s1 += b[pb + (long)hp * Ww] - b[pb + (long)hm * Ww];
        oa[pb + (long)h * Ww] = s0;
        ob[pb + (long)h * Ww] = s1;
    }
}

// ---------------------------------------------------------------------------
// Pass 1c: D-axis running box sum, 2 fields, scaled by 1/729 -> mean fields.
// blockDim = 256 over flattened (b, h*W+w) columns. grid = (B*HW/256, D/CD).
// ---------------------------------------------------------------------------
template<int S0, int S1, int D0, int D1>
__global__ void box_d2_scale() {
    const int c  = blockIdx.x * blockDim.x + threadIdx.x;  // [0, B*HW)
    const int bb = c / HW;
    const int hw = c - bb * HW;
    const long base = (long)bb * DHW + hw;
    const int d0 = blockIdx.y * CD;
    const float* __restrict__ a = g_scratch[S0];
    const float* __restrict__ b = g_scratch[S1];
    float* __restrict__ oa = g_scratch[D0];
    float* __restrict__ ob = g_scratch[D1];

    float s0 = 0.f, s1 = 0.f;
#pragma unroll
    for (int d = -RADI; d <= RADI; ++d) {
        int dd = min(max(d0 + d, 0), Dd - 1);
        s0 += a[base + (long)dd * HW];
        s1 += b[base + (long)dd * HW];
    }
    oa[base + (long)d0 * HW] = s0 * INV_V;
    ob[base + (long)d0 * HW] = s1 * INV_V;
    for (int d = d0 + 1; d < d0 + CD; ++d) {
        int dp = min(d + RADI, Dd - 1);
        int dm = max(d - RADI - 1, 0);
        s0 += a[base + (long)dp * HW] - a[base + (long)dm * HW];
        s1 += b[base + (long)dp * HW] - b[base + (long)dm * HW];
        oa[base + (long)d * HW] = s0 * INV_V;
        ob[base + (long)d * HW] = s1 * INV_V;
    }
}

// ---------------------------------------------------------------------------
// Pass 2a: form tc = t - Mt, pc = p - Mp on the fly, W-axis box sums of
// (tc*pc, tc*tc, pc*pc) via smem. blockDim (160,2), grid 30720.
// ---------------------------------------------------------------------------
template<int MT, int MP, int DA, int DB, int DC>
__global__ void prod_box_w(const float* __restrict__ t, const float* __restrict__ p) {
    __shared__ float sA[2][Ww], sB[2][Ww], sC[2][Ww];
    const int ly = threadIdx.y;
    const int w  = threadIdx.x;
    const long base = (long)(blockIdx.x * 2 + ly) * Ww;
    const float tc = t[base + w] - g_scratch[MT][base + w];
    const float pc = p[base + w] - g_scratch[MP][base + w];
    sA[ly][w] = tc * pc;
    sB[ly][w] = tc * tc;
    sC[ly][w] = pc * pc;
    __syncthreads();
    float a = 0.f, b = 0.f, c = 0.f;
#pragma unroll
    for (int d = -RADI; d <= RADI; ++d) {
        int i = min(max(w + d, 0), Ww - 1);
        a += sA[ly][i];
        b += sB[ly][i];
        c += sC[ly][i];
    }
    g_scratch[DA][base + w] = a;
    g_scratch[DB][base + w] = b;
    g_scratch[DC][base + w] = c;
}

// ---------------------------------------------------------------------------
// Pass 2b: H-axis running box sum, 3 fields.
// ---------------------------------------------------------------------------
template<int S0, int S1, int S2, int D0, int D1, int D2>
__global__ void box_h3() {
    const int w     = threadIdx.x;
    const int plane = blockIdx.x * 2 + threadIdx.y;
    const int h0    = blockIdx.y * CH;
    const float* __restrict__ a = g_scratch[S0];
    const float* __restrict__ b = g_scratch[S1];
    const float* __restrict__ c = g_scratch[S2];
    float* __restrict__ oa = g_scratch[D0];
    float* __restrict__ ob = g_scratch[D1];
    float* __restrict__ oc = g_scratch[D2];
    const long pb = (long)plane * HW + w;

    float s0 = 0.f, s1 = 0.f, s2 = 0.f;
#pragma unroll
    for (int d = -RADI; d <= RADI; ++d) {
        int hh = min(max(h0 + d, 0), Hh - 1);
        s0 += a[pb + (long)hh * Ww];
        s1 += b[pb + (long)hh * Ww];
        s2 += c[pb + (long)hh * Ww];
    }
    oa[pb + (long)h0 * Ww] = s0;
    ob[pb + (long)h0 * Ww] = s1;
    oc[pb + (long)h0 * Ww] = s2;
    for (int h = h0 + 1; h < h0 + CH; ++h) {
        int hp = min(h + RADI, Hh - 1);
        int hm = max(h - RADI - 1, 0);
        s0 += a[pb + (long)hp * Ww] - a[pb + (long)hm * Ww];
        s1 += b[pb + (long)hp * Ww] - b[pb + (long)hm * Ww];
        s2 += c[pb + (long)hp * Ww] - c[pb + (long)hm * Ww];
        oa[pb + (long)h * Ww] = s0;
        ob[pb + (long)h * Ww] = s1;
        oc[pb + (long)h * Ww] = s2;
    }
}

// ---------------------------------------------------------------------------
// Pass 2c: D-axis running box sums of 3 fields, fused with cc computation and
// global reduction (block reduce + one atomicAdd per block).
// ---------------------------------------------------------------------------
template<int SA, int SB, int SC>
__global__ void box_d3_cc(float* __restrict__ out) {
    const int c  = blockIdx.x * blockDim.x + threadIdx.x;
    const int bb = c / HW;
    const int hw = c - bb * HW;
    const long base = (long)bb * DHW + hw;
    const int d0 = blockIdx.y * CD;
    const float* __restrict__ A  = g_scratch[SA];
    const float* __restrict__ Bv = g_scratch[SB];
    const float* __restrict__ Cv = g_scratch[SC];

    float sA = 0.f, sB = 0.f, sC = 0.f;
#pragma unroll
    for (int d = -RADI; d <= RADI; ++d) {
        int dd = min(max(d0 + d, 0), Dd - 1);
        sA += A[base + (long)dd * HW];
        sB += Bv[base + (long)dd * HW];
        sC += Cv[base + (long)dd * HW];
    }
    float acc;
    {
        float num = sA * sA + EPSL;
        float den = sB * sC + EPSL;
        acc = fminf(fmaxf(num / den, 0.f), 1.f);
    }
    for (int d = d0 + 1; d < d0 + CD; ++d) {
        int dp = min(d + RADI, Dd - 1);
        int dm = max(d - RADI - 1, 0);
        sA += A[base + (long)dp * HW] - A[base + (long)dm * HW];
        sB += Bv[base + (long)dp * HW] - Bv[base + (long)dm * HW];
        sC += Cv[base + (long)dp * HW] - Cv[base + (long)dm * HW];
        float num = sA * sA + EPSL;
        float den = sB * sC + EPSL;
        acc += fminf(fmaxf(num / den, 0.f), 1.f);
    }

    __shared__ float red[256];
    red[threadIdx.x] = acc;
    __syncthreads();
#pragma unroll
    for (int s = 128; s > 0; s >>= 1) {
        if (threadIdx.x < s) red[threadIdx.x] += red[threadIdx.x + s];
        __syncthreads();
    }
    if (threadIdx.x == 0) atomicAdd(out, -red[0] * (1.0f / (float)NTOT));
}

__global__ void zero_out_k(float* o) { *o = 0.f; }

// ---------------------------------------------------------------------------
extern "C" void kernel_launch(void* const* d_in, const int* in_sizes, int n_in,
                              void* d_out, int out_size) {
    const float* t = (const float*)d_in[0];  // y_true
    const float* p = (const float*)d_in[1];  // y_pred
    float* out = (float*)d_out;

    const dim3 bw(Ww, 2);                    // 320 threads
    const int linesW = Bsz * Dd * Hh / 2;    // 30720 blocks

    // Pass 1: mean fields -> g_scratch[4] (Mt), g_scratch[5] (Mp)
    box_w2<0, 1><<<linesW, bw>>>(t, p);
    box_h2<0, 1, 2, 3><<<dim3(Bsz * Dd / 2, Hh / CH), bw>>>();
    box_d2_scale<2, 3, 4, 5><<<dim3(Bsz * HW / 256, Dd / CD), 256>>>();

    // Pass 2: centered products -> box sums -> cc -> reduce
    prod_box_w<4, 5, 0, 1, 2><<<linesW, bw>>>(t, p);
    box_h3<0, 1, 2, 3, 4, 5><<<dim3(Bsz * Dd / 2, Hh / CH), bw>>>();
    zero_out_k<<<1, 1>>>(out);
    box_d3_cc<3, 4, 5><<<dim3(Bsz * HW / 256, Dd / CD), 256>>>(out);
}